// round 7
// baseline (speedup 1.0000x reference)
#include <cuda_runtime.h>
#include <stdint.h>

#define NPG  256
#define EPG  4096
#define KTOP 30
#define SA   36    // row stride (floats) for both ping-pong buffers
#define SA2  18    // stride in float2

// ---- dynamic smem layout (bytes) ----
#define OFF_A     0        // 256*36*4 = 36864
#define OFF_B     36864    // 36864
#define OFF_ACC   73728    // 16*256*4 = 16384 (aliases W0 during layer 0)
#define OFF_W0S   73728
#define OFF_CSR   90112    // u8 entries, even-aligned buckets (<=4352 used, 4608 reserved)
#define OFF_W1    94720    // 1024 f32
#define OFF_W2    98816    // 1024 f32
#define OFF_CW1T  102912   // 97x16 f32 = 6208
#define OFF_W3    109120   // 32 f32
#define OFF_B0    109248
#define OFF_B1    109376
#define OFF_B2    109504
#define OFF_B3    109632
#define OFF_DINV  109760   // 256 f32
#define OFF_OC    110784   // 256 u32: bucket_off | (indeg<<16)
#define OFF_CB1   111808   // 16 f32
#define OFF_H4    111872   // 256 f32
#define SMEM_TOTAL 112896  // <= 114688 -> 2 CTAs/SM
// aliases inside B (early): CNT, WS ; (late): KEYS
#define OFF_CNT   OFF_B
#define OFF_WS    (OFF_B + 1024)
#define OFF_KEYS  OFF_B
// late-phase scratch inside A
#define SC_O1   1024
#define SC_PM   2944
#define SC_O2   3904
#define SC_CW2  5312
#define SC_OW   15552
#define SC_CB2  18368
#define SC_OB   18496

extern __shared__ unsigned char smem_raw[];

__device__ __forceinline__ void ffma2(float2& d, const float2 a, const float2 b) {
    asm("fma.rn.f32x2 %0, %1, %2, %0;"
        : "+l"(reinterpret_cast<unsigned long long&>(d))
        : "l"(reinterpret_cast<const unsigned long long&>(const_cast<float2&>(a))),
          "l"(reinterpret_cast<const unsigned long long&>(const_cast<float2&>(b))));
}
__device__ __forceinline__ void add2(float2& d, const float2 a) {
    asm("add.rn.f32x2 %0, %1, %0;"
        : "+l"(reinterpret_cast<unsigned long long&>(d))
        : "l"(reinterpret_cast<const unsigned long long&>(const_cast<float2&>(a))));
}
__device__ __forceinline__ float2 dup2(float a) { return make_float2(a, a); }

__device__ __forceinline__ float fast_tanh(float x) {
    x = fminf(fmaxf(x, -9.f), 9.f);
    float x2 = x * x;
    float p = fmaf(x2, -2.76076847742355e-16f, 2.00018790482477e-13f);
    p = fmaf(x2, p, -8.60467152213735e-11f);
    p = fmaf(x2, p, 5.12229709037114e-08f);
    p = fmaf(x2, p, 1.48572235717979e-05f);
    p = fmaf(x2, p, 6.37261928875436e-04f);
    p = fmaf(x2, p, 4.89352455891786e-03f);
    p *= x;
    float q = fmaf(x2, 1.19825839466702e-06f, 1.18534705686654e-04f);
    q = fmaf(x2, q, 2.26843463243900e-03f);
    q = fmaf(x2, q, 4.89352518554385e-03f);
    return __fdividef(p, q);
}

__device__ __forceinline__ int accidx(int c, int v) {
    return c * 256 + (v ^ ((c & 8) << 1));
}

// Per-warp scatter: pooled = y[v] + sum_in y[src]; Y[v] = tanh((pooled+b)*dinv).
// Reads ALL rows of X (needs barrier before), writes only own 16 rows of Y.
__device__ __forceinline__ void scatter_act_w(const float* __restrict__ X,
                                              float* __restrict__ Y,
                                              const unsigned* __restrict__ OC,
                                              const unsigned char* __restrict__ CSRu8,
                                              const float* __restrict__ bias,
                                              const float* __restrict__ dinv,
                                              int w, int lane)
{
    int el = lane >> 4, ch = lane & 15;
    const float2* X2 = (const float2*)X;
    float bl = bias[2 * ch + el];
    for (int v = w * 16; v < w * 16 + 16; v++) {
        unsigned oc = OC[v];
        unsigned o0 = oc & 0xFFFFu;
        unsigned o1 = o0 + (oc >> 16);
        float2 s0 = (el == 0) ? X2[v * SA2 + ch] : make_float2(0.f, 0.f);
        float2 s1 = make_float2(0.f, 0.f);
        unsigned i = o0 + 2u * (unsigned)el;
        while (i + 1 < o1) {
            unsigned pk = *(const unsigned short*)(CSRu8 + i);   // even-aligned
            unsigned ra = (pk & 0xFFu) * SA2;
            unsigned rb = (pk >> 8) * SA2;
            add2(s0, X2[ra + ch]);
            add2(s1, X2[rb + ch]);
            i += 4;
        }
        if (i < o1) add2(s0, X2[(unsigned)CSRu8[i] * SA2 + ch]);
        add2(s0, s1);
        float sx = s0.x + __shfl_xor_sync(0xffffffffu, s0.x, 16);
        float sy = s0.y + __shfl_xor_sync(0xffffffffu, s0.y, 16);
        float val = el ? sy : sx;
        Y[v * SA + 2 * ch + el] = fast_tanh((val + bl) * dinv[v]);
    }
}

// Per-warp conv1 accumulator pass: ACC[c][v] (+)= dot(Y[v,:], wacc[:,c])
// lane = (pair = lane>>2 -> 2 rows, cg = lane&3 -> 4 of 16 cols)
__device__ __forceinline__ void acc_pass_w(const float* __restrict__ Y,
                                           float* __restrict__ ACC,
                                           const float* __restrict__ wacc, // [32][16]
                                           int w, int lane, bool first)
{
    int pair = lane >> 2, cg = lane & 3;
    int v0 = w * 16 + 2 * pair, v1 = v0 + 1;
    const float4* r0 = (const float4*)(Y + v0 * SA);
    const float4* r1 = (const float4*)(Y + v1 * SA);
    float2 c00 = make_float2(0.f, 0.f), c01 = c00, c10 = c00, c11 = c00;
#pragma unroll
    for (int k4 = 0; k4 < 8; k4++) {
        int kk = (k4 + pair) & 7;          // bank-rotation
        float4 a0 = r0[kk], a1 = r1[kk];
        float av0[4] = {a0.x, a0.y, a0.z, a0.w};
        float av1[4] = {a1.x, a1.y, a1.z, a1.w};
#pragma unroll
        for (int j = 0; j < 4; j++) {
            int k = kk * 4 + j;
            float4 wv = *(const float4*)(wacc + k * 16 + cg * 4);
            float2 wA = make_float2(wv.x, wv.y), wB = make_float2(wv.z, wv.w);
            ffma2(c00, dup2(av0[j]), wA); ffma2(c01, dup2(av0[j]), wB);
            ffma2(c10, dup2(av1[j]), wA); ffma2(c11, dup2(av1[j]), wB);
        }
    }
    float q0[4] = {c00.x, c00.y, c01.x, c01.y};
    float q1[4] = {c10.x, c10.y, c11.x, c11.y};
    if (first) {
#pragma unroll
        for (int j = 0; j < 4; j++) {
            ACC[accidx(cg * 4 + j, v0)] = q0[j];
            ACC[accidx(cg * 4 + j, v1)] = q1[j];
        }
    } else {
#pragma unroll
        for (int j = 0; j < 4; j++) {
            ACC[accidx(cg * 4 + j, v0)] += q0[j];
            ACC[accidx(cg * 4 + j, v1)] += q1[j];
        }
    }
}

// Per-warp IN-PLACE gemm on own 16 rows: Y(rows) = Y(rows) @ W  (32x32)
// lane = (pair -> 2 rows, cg -> 8 cols). __syncwarp before stores.
__device__ __forceinline__ void gemm_inplace_w(float* __restrict__ Y,
                                               const float* __restrict__ Ws,
                                               int w, int lane)
{
    int pair = lane >> 2, cg = lane & 3;
    float* row0 = Y + (w * 16 + 2 * pair) * SA;
    float* row1 = row0 + SA;
    const float4* W4 = (const float4*)Ws;
    float2 o0[4], o1[4];
#pragma unroll
    for (int j = 0; j < 4; j++) { o0[j] = make_float2(0.f, 0.f); o1[j] = o0[j]; }
#pragma unroll
    for (int k4 = 0; k4 < 8; k4++) {
        int kk = (k4 + pair) & 7;
        float4 a0 = ((const float4*)row0)[kk];
        float4 a1 = ((const float4*)row1)[kk];
        float av0[4] = {a0.x, a0.y, a0.z, a0.w};
        float av1[4] = {a1.x, a1.y, a1.z, a1.w};
#pragma unroll
        for (int j = 0; j < 4; j++) {
            int k = kk * 4 + j;
            float4 w0 = W4[k * 8 + cg * 2];
            float4 w1 = W4[k * 8 + cg * 2 + 1];
            float2 wa = make_float2(w0.x, w0.y), wb = make_float2(w0.z, w0.w);
            float2 wc = make_float2(w1.x, w1.y), wd = make_float2(w1.z, w1.w);
            ffma2(o0[0], dup2(av0[j]), wa); ffma2(o0[1], dup2(av0[j]), wb);
            ffma2(o0[2], dup2(av0[j]), wc); ffma2(o0[3], dup2(av0[j]), wd);
            ffma2(o1[0], dup2(av1[j]), wa); ffma2(o1[1], dup2(av1[j]), wb);
            ffma2(o1[2], dup2(av1[j]), wc); ffma2(o1[3], dup2(av1[j]), wd);
        }
    }
    __syncwarp();   // all reads of these rows (acc + gemm) complete before overwrite
    float4* s0 = (float4*)(row0 + cg * 8);
    float4* s1 = (float4*)(row1 + cg * 8);
    s0[0] = make_float4(o0[0].x, o0[0].y, o0[1].x, o0[1].y);
    s0[1] = make_float4(o0[2].x, o0[2].y, o0[3].x, o0[3].y);
    s1[0] = make_float4(o1[0].x, o1[0].y, o1[1].x, o1[1].y);
    s1[1] = make_float4(o1[2].x, o1[2].y, o1[3].x, o1[3].y);
}

__global__ void __launch_bounds__(512, 2)
dgcnn_kernel(const float* __restrict__ feat,
             const int* __restrict__ src, const int* __restrict__ dst,
             const int* __restrict__ degs,
             const float* __restrict__ W0, const float* __restrict__ b0,
             const float* __restrict__ W1, const float* __restrict__ b1,
             const float* __restrict__ W2, const float* __restrict__ b2,
             const float* __restrict__ W3, const float* __restrict__ b3,
             const float* __restrict__ cw1, const float* __restrict__ cb1,
             const float* __restrict__ cw2, const float* __restrict__ cb2,
             const float* __restrict__ ow, const float* __restrict__ ob,
             float* __restrict__ out)
{
    const int g    = blockIdx.x;
    const int tid  = threadIdx.x;
    const int w    = tid >> 5;
    const int lane = tid & 31;

    float* A   = (float*)(smem_raw + OFF_A);
    float* B   = (float*)(smem_raw + OFF_B);
    float* ACC = (float*)(smem_raw + OFF_ACC);
    float* W0s = (float*)(smem_raw + OFF_W0S);
    unsigned char* CSRu8 = (unsigned char*)(smem_raw + OFF_CSR);
    float* W1s = (float*)(smem_raw + OFF_W1);
    float* W2s = (float*)(smem_raw + OFF_W2);
    float* CW1T = (float*)(smem_raw + OFF_CW1T);
    float* W3s = (float*)(smem_raw + OFF_W3);
    float* B0s = (float*)(smem_raw + OFF_B0);
    float* B1s = (float*)(smem_raw + OFF_B1);
    float* B2s = (float*)(smem_raw + OFF_B2);
    float* B3s = (float*)(smem_raw + OFF_B3);
    float* DINV = (float*)(smem_raw + OFF_DINV);
    unsigned* OC  = (unsigned*)(smem_raw + OFF_OC);
    unsigned* CNT = (unsigned*)(smem_raw + OFF_CNT);
    unsigned* WS  = (unsigned*)(smem_raw + OFF_WS);
    unsigned long long* KEYS = (unsigned long long*)(smem_raw + OFF_KEYS);
    float* CB1s = (float*)(smem_raw + OFF_CB1);
    float* H4   = (float*)(smem_raw + OFF_H4);
    float* O1s  = (float*)(smem_raw + OFF_A + SC_O1);
    float* PMs  = (float*)(smem_raw + OFF_A + SC_PM);
    float* O2s  = (float*)(smem_raw + OFF_A + SC_O2);
    float* CW2c = (float*)(smem_raw + OFF_A + SC_CW2);
    float* OWc  = (float*)(smem_raw + OFF_A + SC_OW);
    float* CB2c = (float*)(smem_raw + OFF_A + SC_CB2);
    float* OBc  = (float*)(smem_raw + OFF_A + SC_OB);

    // ---- Phase A: weights, degs, scan, CSR ----
    for (int i = tid; i < 256; i += 512) {
        ((float4*)W1s)[i] = ((const float4*)W1)[i];
        ((float4*)W2s)[i] = ((const float4*)W2)[i];
    }
    for (int i = tid; i < 1024; i += 512) ((float4*)W0s)[i] = ((const float4*)W0)[i];
    for (int i = tid; i < 97 * 16; i += 512) {
        int d = i >> 4, c = i & 15;
        CW1T[i] = cw1[c * 97 + d];
    }
    if (tid < 32) { W3s[tid] = W3[tid]; B0s[tid] = b0[tid]; B1s[tid] = b1[tid]; B2s[tid] = b2[tid]; }
    if (tid == 0) B3s[0] = b3[0];
    if (tid < 16) CB1s[tid] = cb1[tid];

    int indeg = 0;
    unsigned sizev = 0, xincl = 0;
    if (tid < 256) {
        indeg = degs[g * NPG + tid];
        DINV[tid] = 1.0f / (float)(indeg + 1);
        CNT[tid]  = 0u;
        sizev = ((unsigned)indeg + 1u) & ~1u;   // even bucket capacity >= indeg
        xincl = sizev;
#pragma unroll
        for (int d = 1; d < 32; d <<= 1) {
            unsigned t = __shfl_up_sync(0xffffffffu, xincl, d);
            if (lane >= d) xincl += t;
        }
        if (lane == 31) WS[w] = xincl;
    }
    __syncthreads();
    if (tid == 0) {
        unsigned run = 0;
#pragma unroll
        for (int q = 0; q < 8; q++) { unsigned t = WS[q]; WS[q] = run; run += t; }
    }
    __syncthreads();
    if (tid < 256)
        OC[tid] = (xincl + WS[w] - sizev) | ((unsigned)indeg << 16);
    __syncthreads();

    {
        const int gbase = g * NPG;
        const int4* s4 = (const int4*)(src + g * EPG);
        const int4* d4 = (const int4*)(dst + g * EPG);
        for (int e = tid; e < EPG / 4; e += 512) {
            int4 S = s4[e], D = d4[e];
            { int dl = D.x - gbase; unsigned p = atomicAdd(&CNT[dl], 1u);
              CSRu8[(OC[dl] & 0xFFFFu) + p] = (unsigned char)(S.x - gbase); }
            { int dl = D.y - gbase; unsigned p = atomicAdd(&CNT[dl], 1u);
              CSRu8[(OC[dl] & 0xFFFFu) + p] = (unsigned char)(S.y - gbase); }
            { int dl = D.z - gbase; unsigned p = atomicAdd(&CNT[dl], 1u);
              CSRu8[(OC[dl] & 0xFFFFu) + p] = (unsigned char)(S.z - gbase); }
            { int dl = D.w - gbase; unsigned p = atomicAdd(&CNT[dl], 1u);
              CSRu8[(OC[dl] & 0xFFFFu) + p] = (unsigned char)(S.w - gbase); }
        }
    }
    __syncthreads();   // CSR + W0s ready; B (CNT/WS alias) dead

    // ---- layer 0 GEMM from GMEM: feat[256x128] @ W0 -> B ----
    {
        int rp = tid >> 2;     // rows 2rp, 2rp+1
        int cg = tid & 3;      // cols cg*8..+7
        const float4* a0p = (const float4*)(feat + ((size_t)(g * NPG) + 2 * rp) * 128);
        const float4* a1p = a0p + 32;
        const float4* W04 = (const float4*)W0s;
        float2 acc[8];
#pragma unroll
        for (int j = 0; j < 8; j++) acc[j] = make_float2(0.f, 0.f);
        float4 a0c = a0p[0], a1c = a1p[0];
#pragma unroll 4
        for (int k4 = 0; k4 < 32; k4++) {
            float4 a0n = a0c, a1n = a1c;
            if (k4 < 31) { a0n = a0p[k4 + 1]; a1n = a1p[k4 + 1]; }
            float av0[4] = {a0c.x, a0c.y, a0c.z, a0c.w};
            float av1[4] = {a1c.x, a1c.y, a1c.z, a1c.w};
#pragma unroll
            for (int j = 0; j < 4; j++) {
                int k = k4 * 4 + j;
                float4 w0 = W04[k * 8 + cg * 2];
                float4 w1 = W04[k * 8 + cg * 2 + 1];
                float2 r0 = dup2(av0[j]), r1 = dup2(av1[j]);
                ffma2(acc[0], r0, make_float2(w0.x, w0.y));
                ffma2(acc[1], r0, make_float2(w0.z, w0.w));
                ffma2(acc[2], r0, make_float2(w1.x, w1.y));
                ffma2(acc[3], r0, make_float2(w1.z, w1.w));
                ffma2(acc[4], r1, make_float2(w0.x, w0.y));
                ffma2(acc[5], r1, make_float2(w0.z, w0.w));
                ffma2(acc[6], r1, make_float2(w1.x, w1.y));
                ffma2(acc[7], r1, make_float2(w1.z, w1.w));
            }
            a0c = a0n; a1c = a1n;
        }
        float4* st0 = (float4*)(B + 2 * rp * SA + cg * 8);
        st0[0] = make_float4(acc[0].x, acc[0].y, acc[1].x, acc[1].y);
        st0[1] = make_float4(acc[2].x, acc[2].y, acc[3].x, acc[3].y);
        float4* st1 = (float4*)(B + (2 * rp + 1) * SA + cg * 8);
        st1[0] = make_float4(acc[4].x, acc[4].y, acc[5].x, acc[5].y);
        st1[1] = make_float4(acc[6].x, acc[6].y, acc[7].x, acc[7].y);
    }
    __syncthreads();

    // ---- fused per-warp GNN layers (one CTA barrier per layer) ----
    scatter_act_w(B, A, OC, CSRu8, B0s, DINV, w, lane);
    __syncwarp();
    acc_pass_w(A, ACC, CW1T, w, lane, true);
    gemm_inplace_w(A, W1s, w, lane);          // A := y1
    __syncthreads();

    scatter_act_w(A, B, OC, CSRu8, B1s, DINV, w, lane);
    __syncwarp();
    acc_pass_w(B, ACC, CW1T + 32 * 16, w, lane, false);
    gemm_inplace_w(B, W2s, w, lane);          // B := y2
    __syncthreads();

    scatter_act_w(B, A, OC, CSRu8, B2s, DINV, w, lane);   // A := h3
    __syncwarp();
    acc_pass_w(A, ACC, CW1T + 64 * 16, w, lane, false);
    __syncthreads();

    // ---- layer 3 (dout=1): y3 -> B[v*SA] ----
    if (tid < 256) {
        const float4* zr4 = (const float4*)(A + tid * SA);
        float s0 = 0.f, s1 = 0.f, s2 = 0.f, s3 = 0.f;
#pragma unroll
        for (int q = 0; q < 8; q++) {
            float4 z = zr4[q];
            s0 = fmaf(z.x, W3s[4 * q],     s0);
            s1 = fmaf(z.y, W3s[4 * q + 1], s1);
            s2 = fmaf(z.z, W3s[4 * q + 2], s2);
            s3 = fmaf(z.w, W3s[4 * q + 3], s3);
        }
        B[tid * SA] = (s0 + s1) + (s2 + s3);
    }
    __syncthreads();
    // h4 -> H4
    if (tid < 256) {
        unsigned oc = OC[tid];
        unsigned o0 = oc & 0xFFFFu, o1 = o0 + (oc >> 16);
        float s0 = B[tid * SA], s1 = 0.f, s2 = 0.f, s3 = 0.f;
        unsigned i = o0;
        for (; i + 4 <= o1; i += 4) {
            unsigned a = CSRu8[i], b = CSRu8[i + 1], c = CSRu8[i + 2], d = CSRu8[i + 3];
            s0 += B[a * SA]; s1 += B[b * SA]; s2 += B[c * SA]; s3 += B[d * SA];
        }
        for (; i < o1; i++) s0 += B[CSRu8[i] * SA];
        H4[tid] = fast_tanh(((s0 + s1) + (s2 + s3) + B3s[0]) * DINV[tid]);
    }
    __syncthreads();   // B dead -> KEYS region; A dead -> scratch

    // keys (warps 0-7) + CNN-head weight staging (warps 8-15)
    if (tid < 256) {
        unsigned bits = __float_as_uint(H4[tid]);
        unsigned uv = (bits & 0x80000000u) ? ~bits : (bits | 0x80000000u);
        KEYS[tid] = ((unsigned long long)(~uv) << 32) | (unsigned)tid;
    } else {
        int t = tid - 256;
        for (int i = t; i < 640; i += 256) ((float4*)CW2c)[i] = ((const float4*)cw2)[i];
        for (int i = t; i < 176; i += 256) ((float4*)OWc)[i] = ((const float4*)ow)[i];
        if (t < 32) CB2c[t] = cb2[t];
        if (t < 2) OBc[t] = ob[t];
    }
    __syncthreads();

    // bitonic sort 256 u64 keys (warps 0-7 only, named barrier)
    if (tid < 256) {
        for (int k = 2; k <= 256; k <<= 1) {
            for (int j = k >> 1; j > 0; j >>= 1) {
                int ixj = tid ^ j;
                if (ixj > tid) {
                    bool up = ((tid & k) == 0);
                    unsigned long long a = KEYS[tid], b = KEYS[ixj];
                    if ((a > b) == up) { KEYS[tid] = b; KEYS[ixj] = a; }
                }
                asm volatile("bar.sync 1, 256;" ::: "memory");
            }
        }
    }
    __syncthreads();

    // conv1 from ACC (+ h4 term), relu
    if (tid < 480) {
        int c = tid & 15, k = tid >> 4;
        int idx = (int)(KEYS[k] & 0xFFu);
        float s = ACC[accidx(c, idx)] + H4[idx] * CW1T[96 * 16 + c] + CB1s[c];
        O1s[c * KTOP + k] = fmaxf(s, 0.f);
    }
    __syncthreads();
    for (int t = tid; t < 16 * 15; t += 512) {
        int c = t / 15, j = t % 15;
        PMs[c * 15 + j] = fmaxf(O1s[c * KTOP + 2 * j], O1s[c * KTOP + 2 * j + 1]);
    }
    __syncthreads();
    for (int t = tid; t < 32 * 11; t += 512) {
        int c2 = t / 11, tt = t % 11;
        float s = CB2c[c2];
#pragma unroll 4
        for (int c1 = 0; c1 < 16; c1++) {
            const float* wp = CW2c + (c2 * 16 + c1) * 5;
            const float* pp = PMs + c1 * 15 + tt;
#pragma unroll
            for (int kk = 0; kk < 5; kk++) s = fmaf(pp[kk], wp[kk], s);
        }
        O2s[c2 * 11 + tt] = fmaxf(s, 0.f);
    }
    __syncthreads();
    if (tid < 64) {
        int o = tid >> 5, l2 = tid & 31;
        float s = 0.f;
        for (int i = l2; i < 352; i += 32) s = fmaf(O2s[i], OWc[i * 2 + o], s);
#pragma unroll
        for (int d = 16; d > 0; d >>= 1) s += __shfl_down_sync(0xffffffffu, s, d);
        if (l2 == 0) out[g * 2 + o] = fmaxf(s + OBc[o], 0.f);
    }
}

extern "C" void kernel_launch(void* const* d_in, const int* in_sizes, int n_in,
                              void* d_out, int out_size)
{
    const float *feat, *W0, *b0, *W1, *b1, *W2, *b2, *W3, *b3;
    const float *cw1, *cb1, *cw2, *cb2, *ow, *ob;
    const int *src, *dst, *degs;

    if (n_in >= 2 && in_sizes[1] == 1048576) {
        feat = (const float*)d_in[0];
        src  = (const int*)d_in[1];
        dst  = (const int*)d_in[2];
        degs = (const int*)d_in[3];
        W0 = (const float*)d_in[4];  b0 = (const float*)d_in[5];
        W1 = (const float*)d_in[6];  b1 = (const float*)d_in[7];
        W2 = (const float*)d_in[8];  b2 = (const float*)d_in[9];
        W3 = (const float*)d_in[10]; b3 = (const float*)d_in[11];
        cw1 = (const float*)d_in[12]; cb1 = (const float*)d_in[13];
        cw2 = (const float*)d_in[14]; cb2 = (const float*)d_in[15];
        ow  = (const float*)d_in[16]; ob  = (const float*)d_in[17];
    } else {
        feat = (const float*)d_in[0];
        W0 = (const float*)d_in[1];  b0 = (const float*)d_in[2];
        W1 = (const float*)d_in[3];  b1 = (const float*)d_in[4];
        W2 = (const float*)d_in[5];  b2 = (const float*)d_in[6];
        W3 = (const float*)d_in[7];  b3 = (const float*)d_in[8];
        cw1 = (const float*)d_in[9];  cb1 = (const float*)d_in[10];
        cw2 = (const float*)d_in[11]; cb2 = (const float*)d_in[12];
        ow  = (const float*)d_in[13]; ob  = (const float*)d_in[14];
        src  = (const int*)d_in[15];
        dst  = (const int*)d_in[16];
        degs = (const int*)d_in[17];
    }

    cudaFuncSetAttribute(dgcnn_kernel,
                         cudaFuncAttributeMaxDynamicSharedMemorySize, SMEM_TOTAL);
    dgcnn_kernel<<<256, 512, SMEM_TOTAL>>>(
        feat, src, dst, degs,
        W0, b0, W1, b1, W2, b2, W3, b3,
        cw1, cb1, cw2, cb2, ow, ob,
        (float*)d_out);
}

// round 8
// speedup vs baseline: 1.2966x; 1.2966x over previous
#include <cuda_runtime.h>
#include <stdint.h>

#define NPG  256
#define EPG  4096
#define KTOP 30
#define SA   36    // A stride (floats), 144B rows -> float4-aligned
#define SB   34    // B stride (floats)
#define SB2  17    // B stride in float2 (odd -> conflict-free gather)

// ---- dynamic smem layout (bytes) ----
#define OFF_A     0          // 256*36*4 = 36864
#define OFF_B     36864      // 256*34*4 = 34816
#define OFF_ACC   71680      // 16*256*4 = 16384 (aliases W0 during layer 0)
#define OFF_W0S   71680
#define OFF_CSR   88064      // 4096 u16 (entries = src*17)
#define OFF_W1    96256      // 1024 f32
#define OFF_W2    100352
#define OFF_CW1T  104448     // 97x16 f32
#define OFF_W3    110656     // 32 f32
#define OFF_B0    110784
#define OFF_B1    110912
#define OFF_B2    111040
#define OFF_B3    111168
#define OFF_DINV  111296     // 256 f32
#define OFF_COFF  112320     // 257 u32 (pad 1056)
#define OFF_CB1   113376     // 16 f32
#define SMEM_TOTAL 113440
// aliases inside B (early phase): CNT, WS. Late phase: KEYS.
#define OFF_CNT   OFF_B
#define OFF_WS    (OFF_B + 1024)
#define OFF_KEYS  OFF_B
// late-phase scratch inside A (A[0..255] holds h4)
#define SC_O1   1024
#define SC_PM   2944
#define SC_O2   3904
#define SC_CW2  5312
#define SC_OW   15552
#define SC_CB2  18368
#define SC_OB   18496

extern __shared__ unsigned char smem_raw[];

__device__ __forceinline__ void ffma2(float2& d, const float2 a, const float2 b) {
    asm("fma.rn.f32x2 %0, %1, %2, %0;"
        : "+l"(reinterpret_cast<unsigned long long&>(d))
        : "l"(reinterpret_cast<const unsigned long long&>(const_cast<float2&>(a))),
          "l"(reinterpret_cast<const unsigned long long&>(const_cast<float2&>(b))));
}
__device__ __forceinline__ void add2(float2& d, const float2 a) {
    asm("add.rn.f32x2 %0, %1, %0;"
        : "+l"(reinterpret_cast<unsigned long long&>(d))
        : "l"(reinterpret_cast<const unsigned long long&>(const_cast<float2&>(a))));
}
__device__ __forceinline__ float2 dup2(float a) { return make_float2(a, a); }

__device__ __forceinline__ float fast_tanh(float x) {
    x = fminf(fmaxf(x, -9.f), 9.f);
    float x2 = x * x;
    float p = fmaf(x2, -2.76076847742355e-16f, 2.00018790482477e-13f);
    p = fmaf(x2, p, -8.60467152213735e-11f);
    p = fmaf(x2, p, 5.12229709037114e-08f);
    p = fmaf(x2, p, 1.48572235717979e-05f);
    p = fmaf(x2, p, 6.37261928875436e-04f);
    p = fmaf(x2, p, 4.89352455891786e-03f);
    p *= x;
    float q = fmaf(x2, 1.19825839466702e-06f, 1.18534705686654e-04f);
    q = fmaf(x2, q, 2.26843463243900e-03f);
    q = fmaf(x2, q, 4.89352518554385e-03f);
    return __fdividef(p, q);
}

// ACC swizzle: shift v by 8*(c>>2) -> conflict-free for lane=(sub=0..7, q2=0..3)
__device__ __forceinline__ int accidx(int c, int v) {
    return c * 256 + ((v + ((c & 12) << 1)) & 255);
}

// pooled = y[v] + sum_in y[src]; A[v] = tanh((pooled+b)*dinv).
// lanes: el = lane>>4 (edge slot), ch = lane&15 (channel pair). CSR2 = src*17.
__device__ __forceinline__ void scatter_act(const float* __restrict__ Bbuf,
                                            float* __restrict__ Abuf,
                                            const unsigned* __restrict__ OFFA,
                                            const unsigned short* __restrict__ CSR2,
                                            const float* __restrict__ bias,
                                            const float* __restrict__ dinv, int tid)
{
    int w = tid >> 5, lane = tid & 31;
    int el = lane >> 4, ch = lane & 15;
    const float2* B2 = (const float2*)Bbuf;
    float bl = bias[2 * ch + el];
    unsigned o1prev = OFFA[w * 16];
    for (int v = w * 16; v < w * 16 + 16; v++) {
        unsigned o0 = o1prev;
        unsigned o1 = OFFA[v + 1];
        o1prev = o1;
        float2 s0 = (el == 0) ? B2[v * SB2 + ch] : make_float2(0.f, 0.f);
        float2 s1 = make_float2(0.f, 0.f);
        unsigned i = o0 + (unsigned)el;
        while (i + 2 < o1) {
            unsigned a = CSR2[i], b = CSR2[i + 2];
            add2(s0, B2[a + ch]);
            add2(s1, B2[b + ch]);
            i += 4;
        }
        if (i < o1) add2(s0, B2[CSR2[i] + ch]);
        add2(s0, s1);
        float sx = s0.x + __shfl_xor_sync(0xffffffffu, s0.x, 16);
        float sy = s0.y + __shfl_xor_sync(0xffffffffu, s0.y, 16);
        float val = el ? sy : sx;
        Abuf[v * SA + 2 * ch + el] = fast_tanh((val + bl) * dinv[v]);
    }
}

// 256x32 @ 32x32: A (stride SA) -> B (stride SB).
// lane = (sub = lane>>3 -> rows v0+sub+4rr, q = lane&7 -> W float4 col group).
// Each W-load delivers the full 128B W row across the warp (1 wavefront).
__device__ __forceinline__ void gemm32_f2(const float* __restrict__ Ain,
                                          float* __restrict__ Bout,
                                          const float* __restrict__ Ws,
                                          int w, int lane)
{
    int sub = lane >> 3;
    int q   = lane & 7;
    int v0  = w * 16 + sub;
    const float4* W4 = (const float4*)Ws;
    const float4* ar0 = (const float4*)(Ain + v0 * SA);
    const float4* ar1 = (const float4*)(Ain + (v0 + 4) * SA);
    const float4* ar2 = (const float4*)(Ain + (v0 + 8) * SA);
    const float4* ar3 = (const float4*)(Ain + (v0 + 12) * SA);
    float2 acc[4][2];
#pragma unroll
    for (int rr = 0; rr < 4; rr++) {
        acc[rr][0] = make_float2(0.f, 0.f);
        acc[rr][1] = make_float2(0.f, 0.f);
    }
#pragma unroll
    for (int k4 = 0; k4 < 8; k4++) {
        float4 a[4];
        a[0] = ar0[k4]; a[1] = ar1[k4]; a[2] = ar2[k4]; a[3] = ar3[k4];
#pragma unroll
        for (int j = 0; j < 4; j++) {
            float4 wv = W4[(k4 * 4 + j) * 8 + q];
            float2 wlo = make_float2(wv.x, wv.y);
            float2 whi = make_float2(wv.z, wv.w);
#pragma unroll
            for (int rr = 0; rr < 4; rr++) {
                float av = (j == 0) ? a[rr].x : (j == 1) ? a[rr].y
                         : (j == 2) ? a[rr].z : a[rr].w;
                ffma2(acc[rr][0], dup2(av), wlo);
                ffma2(acc[rr][1], dup2(av), whi);
            }
        }
    }
#pragma unroll
    for (int rr = 0; rr < 4; rr++) {
        float2* st = (float2*)Bout + (v0 + 4 * rr) * SB2 + 2 * q;
        st[0] = acc[rr][0];
        st[1] = acc[rr][1];
    }
}

// ACC[c][v] (+)= dot(A[v,0:32], wacc[:,c]).
// lane = (sub = lane>>2 -> rows v0+sub, v0+sub+8; q2 = lane&3 -> 4 of 16 cols).
__device__ __forceinline__ void acc_pass(const float* __restrict__ Ain,
                                         float* __restrict__ ACC,
                                         const float* __restrict__ wacc, // [32][16]
                                         int w, int lane, bool first)
{
    int sub = lane >> 2;
    int q2  = lane & 3;
    int v0  = w * 16 + sub;
    const float4* r0 = (const float4*)(Ain + v0 * SA);
    const float4* r1 = (const float4*)(Ain + (v0 + 8) * SA);
    float2 c00 = make_float2(0.f, 0.f), c01 = c00, c10 = c00, c11 = c00;
#pragma unroll
    for (int k4 = 0; k4 < 8; k4++) {
        float4 a0 = r0[k4], a1 = r1[k4];
#pragma unroll
        for (int j = 0; j < 4; j++) {
            float4 wv = *(const float4*)(wacc + (k4 * 4 + j) * 16 + q2 * 4);
            float2 wlo = make_float2(wv.x, wv.y);
            float2 whi = make_float2(wv.z, wv.w);
            float av0 = (j == 0) ? a0.x : (j == 1) ? a0.y : (j == 2) ? a0.z : a0.w;
            float av1 = (j == 0) ? a1.x : (j == 1) ? a1.y : (j == 2) ? a1.z : a1.w;
            ffma2(c00, dup2(av0), wlo); ffma2(c01, dup2(av0), whi);
            ffma2(c10, dup2(av1), wlo); ffma2(c11, dup2(av1), whi);
        }
    }
    float q0[4] = {c00.x, c00.y, c01.x, c01.y};
    float q1[4] = {c10.x, c10.y, c11.x, c11.y};
    int cb = q2 * 4;
    if (first) {
#pragma unroll
        for (int cc = 0; cc < 4; cc++) {
            ACC[accidx(cb + cc, v0)]     = q0[cc];
            ACC[accidx(cb + cc, v0 + 8)] = q1[cc];
        }
    } else {
#pragma unroll
        for (int cc = 0; cc < 4; cc++) {
            ACC[accidx(cb + cc, v0)]     += q0[cc];
            ACC[accidx(cb + cc, v0 + 8)] += q1[cc];
        }
    }
}

__global__ void __launch_bounds__(512, 2)
dgcnn_kernel(const float* __restrict__ feat,
             const int* __restrict__ src, const int* __restrict__ dst,
             const int* __restrict__ degs,
             const float* __restrict__ W0, const float* __restrict__ b0,
             const float* __restrict__ W1, const float* __restrict__ b1,
             const float* __restrict__ W2, const float* __restrict__ b2,
             const float* __restrict__ W3, const float* __restrict__ b3,
             const float* __restrict__ cw1, const float* __restrict__ cb1,
             const float* __restrict__ cw2, const float* __restrict__ cb2,
             const float* __restrict__ ow, const float* __restrict__ ob,
             float* __restrict__ out)
{
    const int g    = blockIdx.x;
    const int tid  = threadIdx.x;
    const int w    = tid >> 5;
    const int lane = tid & 31;

    float* A   = (float*)(smem_raw + OFF_A);
    float* B   = (float*)(smem_raw + OFF_B);
    float* ACC = (float*)(smem_raw + OFF_ACC);
    float* W0s = (float*)(smem_raw + OFF_W0S);
    unsigned short* CSR2 = (unsigned short*)(smem_raw + OFF_CSR);
    float* W1s = (float*)(smem_raw + OFF_W1);
    float* W2s = (float*)(smem_raw + OFF_W2);
    float* CW1T = (float*)(smem_raw + OFF_CW1T);
    float* W3s = (float*)(smem_raw + OFF_W3);
    float* B0s = (float*)(smem_raw + OFF_B0);
    float* B1s = (float*)(smem_raw + OFF_B1);
    float* B2s = (float*)(smem_raw + OFF_B2);
    float* B3s = (float*)(smem_raw + OFF_B3);
    float* DINV = (float*)(smem_raw + OFF_DINV);
    unsigned* COFF = (unsigned*)(smem_raw + OFF_COFF);
    unsigned* CNT  = (unsigned*)(smem_raw + OFF_CNT);
    unsigned* WS   = (unsigned*)(smem_raw + OFF_WS);
    unsigned long long* KEYS = (unsigned long long*)(smem_raw + OFF_KEYS);
    float* CB1s = (float*)(smem_raw + OFF_CB1);
    float* O1s  = (float*)(smem_raw + OFF_A + SC_O1);
    float* PMs  = (float*)(smem_raw + OFF_A + SC_PM);
    float* O2s  = (float*)(smem_raw + OFF_A + SC_O2);
    float* CW2c = (float*)(smem_raw + OFF_A + SC_CW2);
    float* OWc  = (float*)(smem_raw + OFF_A + SC_OW);
    float* CB2c = (float*)(smem_raw + OFF_A + SC_CB2);
    float* OBc  = (float*)(smem_raw + OFF_A + SC_OB);

    // ---- Phase A: weights, degs, scan, CSR ----
    for (int i = tid; i < 256; i += 512) {
        ((float4*)W1s)[i] = ((const float4*)W1)[i];
        ((float4*)W2s)[i] = ((const float4*)W2)[i];
    }
    for (int i = tid; i < 1024; i += 512) ((float4*)W0s)[i] = ((const float4*)W0)[i];
    for (int i = tid; i < 97 * 16; i += 512) {
        int d = i >> 4, c = i & 15;
        CW1T[i] = cw1[c * 97 + d];
    }
    if (tid < 32) { W3s[tid] = W3[tid]; B0s[tid] = b0[tid]; B1s[tid] = b1[tid]; B2s[tid] = b2[tid]; }
    if (tid == 0) B3s[0] = b3[0];
    if (tid < 16) CB1s[tid] = cb1[tid];

    int indeg = 0;
    unsigned xincl = 0;
    if (tid < 256) {
        indeg = degs[g * NPG + tid];
        DINV[tid] = 1.0f / (float)(indeg + 1);
        CNT[tid]  = 0u;
        xincl = (unsigned)indeg;
#pragma unroll
        for (int d = 1; d < 32; d <<= 1) {
            unsigned t = __shfl_up_sync(0xffffffffu, xincl, d);
            if (lane >= d) xincl += t;
        }
        if (lane == 31) WS[w] = xincl;
    }
    __syncthreads();
    if (tid == 0) {
        unsigned run = 0;
#pragma unroll
        for (int q = 0; q < 8; q++) { unsigned t = WS[q]; WS[q] = run; run += t; }
    }
    __syncthreads();
    if (tid < 256) COFF[tid] = xincl + WS[w] - (unsigned)indeg;
    if (tid == 0) COFF[256] = EPG;
    __syncthreads();

    {
        const int gbase = g * NPG;
        const int4* s4 = (const int4*)(src + g * EPG);
        const int4* d4 = (const int4*)(dst + g * EPG);
        for (int e = tid; e < EPG / 4; e += 512) {
            int4 S = s4[e], D = d4[e];
            { int dl = D.x - gbase; unsigned p = atomicAdd(&CNT[dl], 1u);
              CSR2[COFF[dl] + p] = (unsigned short)((S.x - gbase) * SB2); }
            { int dl = D.y - gbase; unsigned p = atomicAdd(&CNT[dl], 1u);
              CSR2[COFF[dl] + p] = (unsigned short)((S.y - gbase) * SB2); }
            { int dl = D.z - gbase; unsigned p = atomicAdd(&CNT[dl], 1u);
              CSR2[COFF[dl] + p] = (unsigned short)((S.z - gbase) * SB2); }
            { int dl = D.w - gbase; unsigned p = atomicAdd(&CNT[dl], 1u);
              CSR2[COFF[dl] + p] = (unsigned short)((S.w - gbase) * SB2); }
        }
    }
    __syncthreads();   // CSR + W0s ready; B (CNT alias) now dead

    // ---- layer 0 GEMM directly from GMEM: feat[256x128] @ W0 -> B ----
    {
        int rp = tid >> 2;     // rows 2rp, 2rp+1
        int cg = tid & 3;      // cols cg*8..+7
        const float4* a0p = (const float4*)(feat + ((size_t)(g * NPG) + 2 * rp) * 128);
        const float4* a1p = a0p + 32;
        const float4* W04 = (const float4*)W0s;
        float2 acc[8];
#pragma unroll
        for (int j = 0; j < 8; j++) acc[j] = make_float2(0.f, 0.f);
        float4 a0c = a0p[0], a1c = a1p[0];
#pragma unroll 4
        for (int k4 = 0; k4 < 32; k4++) {
            float4 a0n = a0c, a1n = a1c;
            if (k4 < 31) { a0n = a0p[k4 + 1]; a1n = a1p[k4 + 1]; }
            float av0[4] = {a0c.x, a0c.y, a0c.z, a0c.w};
            float av1[4] = {a1c.x, a1c.y, a1c.z, a1c.w};
#pragma unroll
            for (int j = 0; j < 4; j++) {
                int k = k4 * 4 + j;
                float4 w0 = W04[k * 8 + cg * 2];
                float4 w1 = W04[k * 8 + cg * 2 + 1];
                float2 r0 = dup2(av0[j]), r1 = dup2(av1[j]);
                ffma2(acc[0], r0, make_float2(w0.x, w0.y));
                ffma2(acc[1], r0, make_float2(w0.z, w0.w));
                ffma2(acc[2], r0, make_float2(w1.x, w1.y));
                ffma2(acc[3], r0, make_float2(w1.z, w1.w));
                ffma2(acc[4], r1, make_float2(w0.x, w0.y));
                ffma2(acc[5], r1, make_float2(w0.z, w0.w));
                ffma2(acc[6], r1, make_float2(w1.x, w1.y));
                ffma2(acc[7], r1, make_float2(w1.z, w1.w));
            }
            a0c = a0n; a1c = a1n;
        }
        float4* st0 = (float4*)(B + 2 * rp * SB + cg * 8);
        st0[0] = make_float4(acc[0].x, acc[0].y, acc[1].x, acc[1].y);
        st0[1] = make_float4(acc[2].x, acc[2].y, acc[3].x, acc[3].y);
        float2* st1 = (float2*)(B + (2 * rp + 1) * SB + cg * 8);
        st1[0] = acc[4]; st1[1] = acc[5]; st1[2] = acc[6]; st1[3] = acc[7];
    }
    __syncthreads();

    // ---- GNN layers ----
    scatter_act(B, A, COFF, CSR2, B0s, DINV, tid);
    __syncwarp();
    acc_pass(A, ACC, CW1T, w, lane, true);
    __syncthreads();
    gemm32_f2(A, B, W1s, w, lane);
    __syncthreads();
    scatter_act(B, A, COFF, CSR2, B1s, DINV, tid);
    __syncwarp();
    acc_pass(A, ACC, CW1T + 32 * 16, w, lane, false);
    __syncthreads();
    gemm32_f2(A, B, W2s, w, lane);
    __syncthreads();
    scatter_act(B, A, COFF, CSR2, B2s, DINV, tid);
    __syncwarp();
    acc_pass(A, ACC, CW1T + 64 * 16, w, lane, false);
    __syncthreads();

    // layer 3 (dout=1): y3 -> B[v*SB]
    if (tid < 256) {
        const float4* zr4 = (const float4*)(A + tid * SA);
        float s0 = 0.f, s1 = 0.f, s2 = 0.f, s3 = 0.f;
#pragma unroll
        for (int q = 0; q < 8; q++) {
            float4 z = zr4[q];
            s0 = fmaf(z.x, W3s[4 * q],     s0);
            s1 = fmaf(z.y, W3s[4 * q + 1], s1);
            s2 = fmaf(z.z, W3s[4 * q + 2], s2);
            s3 = fmaf(z.w, W3s[4 * q + 3], s3);
        }
        B[tid * SB] = (s0 + s1) + (s2 + s3);
    }
    __syncthreads();
    // h4 -> A[0..255]
    if (tid < 256) {
        unsigned o0 = COFF[tid], o1 = COFF[tid + 1];
        float s0 = B[tid * SB], s1 = 0.f, s2 = 0.f, s3 = 0.f;
        unsigned i = o0;
        for (; i + 4 <= o1; i += 4) {
            unsigned a = CSR2[i], b = CSR2[i + 1], c = CSR2[i + 2], d = CSR2[i + 3];
            s0 += B[a * 2]; s1 += B[b * 2]; s2 += B[c * 2]; s3 += B[d * 2];
        }
        for (; i < o1; i++) s0 += B[CSR2[i] * 2];
        A[tid] = fast_tanh(((s0 + s1) + (s2 + s3) + B3s[0]) * DINV[tid]);
    }
    __syncthreads();   // B dead -> KEYS region

    // keys (warps 0-7) + CNN-head weight staging (warps 8-15)
    if (tid < 256) {
        unsigned bits = __float_as_uint(A[tid]);
        unsigned uv = (bits & 0x80000000u) ? ~bits : (bits | 0x80000000u);
        KEYS[tid] = ((unsigned long long)(~uv) << 32) | (unsigned)tid;
    } else {
        int t = tid - 256;
        for (int i = t; i < 640; i += 256) ((float4*)CW2c)[i] = ((const float4*)cw2)[i];
        for (int i = t; i < 176; i += 256) ((float4*)OWc)[i] = ((const float4*)ow)[i];
        if (t < 32) CB2c[t] = cb2[t];
        if (t < 2) OBc[t] = ob[t];
    }
    __syncthreads();

    // bitonic sort 256 u64 keys (warps 0-7 only, named barrier)
    if (tid < 256) {
        for (int k = 2; k <= 256; k <<= 1) {
            for (int j = k >> 1; j > 0; j >>= 1) {
                int ixj = tid ^ j;
                if (ixj > tid) {
                    bool up = ((tid & k) == 0);
                    unsigned long long a = KEYS[tid], b = KEYS[ixj];
                    if ((a > b) == up) { KEYS[tid] = b; KEYS[ixj] = a; }
                }
                asm volatile("bar.sync 1, 256;" ::: "memory");
            }
        }
    }
    __syncthreads();

    // conv1 from ACC (+ h4 term), relu
    if (tid < 480) {
        int c = tid & 15, k = tid >> 4;
        int idx = (int)(KEYS[k] & 0xFFu);
        float s = ACC[accidx(c, idx)] + A[idx] * CW1T[96 * 16 + c] + CB1s[c];
        O1s[c * KTOP + k] = fmaxf(s, 0.f);
    }
    __syncthreads();
    for (int t = tid; t < 16 * 15; t += 512) {
        int c = t / 15, j = t % 15;
        PMs[c * 15 + j] = fmaxf(O1s[c * KTOP + 2 * j], O1s[c * KTOP + 2 * j + 1]);
    }
    __syncthreads();
    for (int t = tid; t < 32 * 11; t += 512) {
        int c2 = t / 11, tt = t % 11;
        float s = CB2c[c2];
#pragma unroll 4
        for (int c1 = 0; c1 < 16; c1++) {
            const float* wp = CW2c + (c2 * 16 + c1) * 5;
            const float* pp = PMs + c1 * 15 + tt;
#pragma unroll
            for (int kk = 0; kk < 5; kk++) s = fmaf(pp[kk], wp[kk], s);
        }
        O2s[c2 * 11 + tt] = fmaxf(s, 0.f);
    }
    __syncthreads();
    if (tid < 64) {
        int o = tid >> 5, l2 = tid & 31;
        float s = 0.f;
        for (int i = l2; i < 352; i += 32) s = fmaf(O2s[i], OWc[i * 2 + o], s);
#pragma unroll
        for (int d = 16; d > 0; d >>= 1) s += __shfl_down_sync(0xffffffffu, s, d);
        if (l2 == 0) out[g * 2 + o] = fmaxf(s + OBc[o], 0.f);
    }
}

extern "C" void kernel_launch(void* const* d_in, const int* in_sizes, int n_in,
                              void* d_out, int out_size)
{
    const float *feat, *W0, *b0, *W1, *b1, *W2, *b2, *W3, *b3;
    const float *cw1, *cb1, *cw2, *cb2, *ow, *ob;
    const int *src, *dst, *degs;

    if (n_in >= 2 && in_sizes[1] == 1048576) {
        feat = (const float*)d_in[0];
        src  = (const int*)d_in[1];
        dst  = (const int*)d_in[2];
        degs = (const int*)d_in[3];
        W0 = (const float*)d_in[4];  b0 = (const float*)d_in[5];
        W1 = (const float*)d_in[6];  b1 = (const float*)d_in[7];
        W2 = (const float*)d_in[8];  b2 = (const float*)d_in[9];
        W3 = (const float*)d_in[10]; b3 = (const float*)d_in[11];
        cw1 = (const float*)d_in[12]; cb1 = (const float*)d_in[13];
        cw2 = (const float*)d_in[14]; cb2 = (const float*)d_in[15];
        ow  = (const float*)d_in[16]; ob  = (const float*)d_in[17];
    } else {
        feat = (const float*)d_in[0];
        W0 = (const float*)d_in[1];  b0 = (const float*)d_in[2];
        W1 = (const float*)d_in[3];  b1 = (const float*)d_in[4];
        W2 = (const float*)d_in[5];  b2 = (const float*)d_in[6];
        W3 = (const float*)d_in[7];  b3 = (const float*)d_in[8];
        cw1 = (const float*)d_in[9];  cb1 = (const float*)d_in[10];
        cw2 = (const float*)d_in[11]; cb2 = (const float*)d_in[12];
        ow  = (const float*)d_in[13]; ob  = (const float*)d_in[14];
        src  = (const int*)d_in[15];
        dst  = (const int*)d_in[16];
        degs = (const int*)d_in[17];
    }

    cudaFuncSetAttribute(dgcnn_kernel,
                         cudaFuncAttributeMaxDynamicSharedMemorySize, SMEM_TOTAL);
    dgcnn_kernel<<<256, 512, SMEM_TOTAL>>>(
        feat, src, dst, degs,
        W0, b0, W1, b1, W2, b2, W3, b3,
        cw1, cb1, cw2, cb2, ow, ob,
        (float*)d_out);
}